// round 1
// baseline (speedup 1.0000x reference)
#include <cuda_runtime.h>
#include <cuda_bf16.h>

// DirGCNConv: out = a*(Anorm @ x) @ Wsd^T + (1-a)*(Anorm^T @ x) @ Wds^T + biases
// Restructured: xs = x @ (a*Wsd)^T ; xt = x @ ((1-a)*Wds)^T ; out init to combined
// bias; scatter val(e)*xs[col]->out[row], val(e)*xt[row]->out[col].

#define MAXN 50000
#define D    96
#define D4   24            // D/4 float4 chunks
#define ALPHA 0.5f

// -------- scratch (no runtime allocation allowed) --------
__device__ float g_odeg[MAXN];
__device__ float g_ideg[MAXN];
__device__ float g_ois [MAXN];
__device__ float g_iis [MAXN];
__device__ float g_xs  [MAXN * D];
__device__ float g_xt  [MAXN * D];

// -------- vec4 global float reduction (sm_90+) --------
__device__ __forceinline__ void red4(float4* p, float a, float b, float c, float d) {
    asm volatile("red.global.add.v4.f32 [%0], {%1,%2,%3,%4};"
                 :: "l"(p), "f"(a), "f"(b), "f"(c), "f"(d) : "memory");
}

// ---------------- kernels ----------------

__global__ void zero_deg_kernel(int N) {
    int i = blockIdx.x * blockDim.x + threadIdx.x;
    if (i < N) { g_odeg[i] = 0.0f; g_ideg[i] = 0.0f; }
}

__global__ void deg_kernel(const int* __restrict__ ei, int E) {
    int e = blockIdx.x * blockDim.x + threadIdx.x;
    if (e >= E) return;
    atomicAdd(&g_odeg[ei[e]],     1.0f);   // row
    atomicAdd(&g_ideg[ei[E + e]], 1.0f);   // col
}

__global__ void rsqrt_kernel(int N) {
    int i = blockIdx.x * blockDim.x + threadIdx.x;
    if (i >= N) return;
    float od = g_odeg[i], id = g_ideg[i];
    g_ois[i] = (od > 0.0f) ? rsqrtf(od) : 0.0f;
    g_iis[i] = (id > 0.0f) ? rsqrtf(id) : 0.0f;
}

// Fused dual GEMM: xs[n,j] = sum_k x[n,k]*(a*Wsd[j,k]); xt likewise with (1-a)*Wds.
// Block: 256 threads, 32-node tile, 192 "columns" (96 xs + 96 xt).
// Thread microtile: 4 nodes x 6 cols = 24 accumulators.
#define GEMM_THREADS 256
#define NODE_TILE    32
#define WPAD         97   // padded row stride to avoid bank conflicts

__global__ void gemm_kernel(const float* __restrict__ x,
                            const float* __restrict__ Wsd,
                            const float* __restrict__ Wds,
                            int N) {
    extern __shared__ float sm[];
    float* Wc  = sm;                 // [192][WPAD]
    float* xsm = sm + 192 * WPAD;    // [NODE_TILE][WPAD]

    int tid = threadIdx.x;

    // load + scale weights: rows 0..95 = a*Wsd, rows 96..191 = (1-a)*Wds
    for (int i = tid; i < D * D; i += GEMM_THREADS) {
        int j = i / D, k = i % D;
        Wc[j * WPAD + k]        = ALPHA        * Wsd[i];
        Wc[(j + D) * WPAD + k]  = (1.0f-ALPHA) * Wds[i];
    }
    int nb = blockIdx.x * NODE_TILE;
    for (int i = tid; i < NODE_TILE * D; i += GEMM_THREADS) {
        int r = i / D, k = i % D;
        int n = nb + r;
        xsm[r * WPAD + k] = (n < N) ? x[n * D + k] : 0.0f;
    }
    __syncthreads();

    int tx = tid & 7;    // node group: 4 nodes
    int ty = tid >> 3;   // col group: 6 cols

    float acc[4][6];
#pragma unroll
    for (int i = 0; i < 4; i++)
#pragma unroll
        for (int c = 0; c < 6; c++) acc[i][c] = 0.0f;

    const float* xbase = &xsm[(tx * 4) * WPAD];
    const float* wbase = &Wc [(ty * 6) * WPAD];

#pragma unroll 8
    for (int k = 0; k < D; k++) {
        float xv[4], wv[6];
#pragma unroll
        for (int i = 0; i < 4; i++) xv[i] = xbase[i * WPAD + k];
#pragma unroll
        for (int c = 0; c < 6; c++) wv[c] = wbase[c * WPAD + k];
#pragma unroll
        for (int i = 0; i < 4; i++)
#pragma unroll
            for (int c = 0; c < 6; c++) acc[i][c] += xv[i] * wv[c];
    }

#pragma unroll
    for (int i = 0; i < 4; i++) {
        int n = nb + tx * 4 + i;
        if (n >= N) continue;
#pragma unroll
        for (int c = 0; c < 6; c++) {
            int col = ty * 6 + c;
            if (col < D) g_xs[n * D + col]       = acc[i][c];
            else         g_xt[n * D + (col - D)] = acc[i][c];
        }
    }
}

__global__ void bias_kernel(float* __restrict__ out,
                            const float* __restrict__ b_sd,
                            const float* __restrict__ b_ds, int total) {
    int i = blockIdx.x * blockDim.x + threadIdx.x;
    if (i >= total) return;
    int j = i % D;
    out[i] = ALPHA * __ldg(&b_sd[j]) + (1.0f - ALPHA) * __ldg(&b_ds[j]);
}

// Scatter: 8 threads per edge, each thread handles 3 float4 chunks per direction.
__global__ void scatter_kernel(const int* __restrict__ ei, float* __restrict__ out,
                               int E) {
    int gt = blockIdx.x * blockDim.x + threadIdx.x;
    int e    = gt >> 3;
    int lane = gt & 7;
    if (e >= E) return;

    int row = __ldg(&ei[e]);
    int col = __ldg(&ei[E + e]);
    float val = __ldg(&g_ois[row]) * __ldg(&g_iis[col]);

    const float4* xs4 = reinterpret_cast<const float4*>(g_xs);
    const float4* xt4 = reinterpret_cast<const float4*>(g_xt);
    float4* out4 = reinterpret_cast<float4*>(out);

#pragma unroll
    for (int t = 0; t < 3; t++) {
        int c = lane + t * 8;
        float4 v = __ldg(&xs4[col * D4 + c]);     // message col -> row
        red4(&out4[row * D4 + c], val * v.x, val * v.y, val * v.z, val * v.w);
        float4 u = __ldg(&xt4[row * D4 + c]);     // message row -> col
        red4(&out4[col * D4 + c], val * u.x, val * u.y, val * u.z, val * u.w);
    }
}

// ---------------- launch ----------------

extern "C" void kernel_launch(void* const* d_in, const int* in_sizes, int n_in,
                              void* d_out, int out_size) {
    const float* x    = (const float*)d_in[0];
    const float* Wsd  = (const float*)d_in[1];
    const float* b_sd = (const float*)d_in[2];
    const float* Wds  = (const float*)d_in[3];
    const float* b_ds = (const float*)d_in[4];
    const int*   ei   = (const int*)  d_in[5];
    float* out = (float*)d_out;

    int N = in_sizes[0] / D;
    int E = in_sizes[5] / 2;

    // dynamic smem for the dual GEMM (> 48KB)
    size_t smem = (size_t)(192 * WPAD + NODE_TILE * WPAD) * sizeof(float);
    cudaFuncSetAttribute(gemm_kernel, cudaFuncAttributeMaxDynamicSharedMemorySize,
                         (int)smem);

    zero_deg_kernel<<<(N + 255) / 256, 256>>>(N);
    deg_kernel<<<(E + 255) / 256, 256>>>(ei, E);
    rsqrt_kernel<<<(N + 255) / 256, 256>>>(N);
    gemm_kernel<<<(N + NODE_TILE - 1) / NODE_TILE, GEMM_THREADS, smem>>>(x, Wsd, Wds, N);
    bias_kernel<<<(N * D + 255) / 256, 256>>>(out, b_sd, b_ds, N * D);
    long long sthreads = (long long)E * 8;
    scatter_kernel<<<(int)((sthreads + 255) / 256), 256>>>(ei, out, E);
}

// round 2
// speedup vs baseline: 1.4048x; 1.4048x over previous
#include <cuda_runtime.h>
#include <cuda_bf16.h>

// DirGCNConv restructured:
//   xs = x @ (a*Wsd)^T ; xt = x @ ((1-a)*Wds)^T         (fused dual GEMM)
//   CSR (by row) + CSC (by col) built via counting sort on degrees
//   out[n] = bias + sum_{e: row=n} val(e)*xs[col(e)] + sum_{e: col=n} val(e)*xt[row(e)]
// One coalesced write per output row; no fp atomics.

#define MAXN 50048
#define MAXE 810000
#define D    96
#define D4   24
#define ALPHA 0.5f

// -------- static scratch --------
__device__ int   g_odeg [MAXN];
__device__ int   g_ideg [MAXN];
__device__ float g_ois  [MAXN];
__device__ float g_iis  [MAXN];
__device__ int   g_startR[MAXN];
__device__ int   g_startC[MAXN];
__device__ int   g_curR [MAXN];
__device__ int   g_curC [MAXN];
__device__ int   g_bsumR[256];
__device__ int   g_bsumC[256];
__device__ int   g_boffR[256];
__device__ int   g_boffC[256];
__device__ int   g_idxR [MAXE];
__device__ int   g_idxC [MAXE];
__device__ float g_valR [MAXE];
__device__ float g_valC [MAXE];
__device__ float g_xs   [MAXN * D];
__device__ float g_xt   [MAXN * D];

// ---------------- degree / norm ----------------

__global__ void zero_kernel(int N) {
    int i = blockIdx.x * blockDim.x + threadIdx.x;
    if (i < N) { g_odeg[i] = 0; g_ideg[i] = 0; }
}

__global__ void deg_kernel(const int* __restrict__ ei, int E) {
    int e = blockIdx.x * blockDim.x + threadIdx.x;
    if (e >= E) return;
    atomicAdd(&g_odeg[ei[e]],     1);
    atomicAdd(&g_ideg[ei[E + e]], 1);
}

__global__ void rsqrt_kernel(int N) {
    int i = blockIdx.x * blockDim.x + threadIdx.x;
    if (i >= N) return;
    int od = g_odeg[i], id = g_ideg[i];
    g_ois[i] = (od > 0) ? rsqrtf((float)od) : 0.0f;
    g_iis[i] = (id > 0) ? rsqrtf((float)id) : 0.0f;
}

// ---------------- prefix scan (3 phases) ----------------

__global__ void scan1_kernel(int N) {
    __shared__ int sR[256], sC[256];
    int t = threadIdx.x;
    int i = blockIdx.x * 256 + t;
    int vR = (i < N) ? g_odeg[i] : 0;
    int vC = (i < N) ? g_ideg[i] : 0;
    sR[t] = vR; sC[t] = vC;
    __syncthreads();
#pragma unroll
    for (int off = 1; off < 256; off <<= 1) {
        int aR = (t >= off) ? sR[t - off] : 0;
        int aC = (t >= off) ? sC[t - off] : 0;
        __syncthreads();
        sR[t] += aR; sC[t] += aC;
        __syncthreads();
    }
    if (i < N) { g_startR[i] = sR[t] - vR; g_startC[i] = sC[t] - vC; }
    if (t == 255) { g_bsumR[blockIdx.x] = sR[255]; g_bsumC[blockIdx.x] = sC[255]; }
}

__global__ void scan2_kernel(int nblocks) {
    __shared__ int sR[256], sC[256];
    int t = threadIdx.x;
    int vR = (t < nblocks) ? g_bsumR[t] : 0;
    int vC = (t < nblocks) ? g_bsumC[t] : 0;
    sR[t] = vR; sC[t] = vC;
    __syncthreads();
#pragma unroll
    for (int off = 1; off < 256; off <<= 1) {
        int aR = (t >= off) ? sR[t - off] : 0;
        int aC = (t >= off) ? sC[t - off] : 0;
        __syncthreads();
        sR[t] += aR; sC[t] += aC;
        __syncthreads();
    }
    if (t < nblocks) { g_boffR[t] = sR[t] - vR; g_boffC[t] = sC[t] - vC; }
}

__global__ void scan3_kernel(int N) {
    int i = blockIdx.x * blockDim.x + threadIdx.x;
    if (i >= N) return;
    int b = i >> 8;
    int sR = g_startR[i] + g_boffR[b];
    int sC = g_startC[i] + g_boffC[b];
    g_startR[i] = sR; g_curR[i] = sR;
    g_startC[i] = sC; g_curC[i] = sC;
}

// ---------------- CSR/CSC build ----------------

__global__ void build_kernel(const int* __restrict__ ei, int E) {
    int e = blockIdx.x * blockDim.x + threadIdx.x;
    if (e >= E) return;
    int r = ei[e];
    int c = ei[E + e];
    float val = g_ois[r] * g_iis[c];
    int pR = atomicAdd(&g_curR[r], 1);
    g_idxR[pR] = c; g_valR[pR] = val;
    int pC = atomicAdd(&g_curC[c], 1);
    g_idxC[pC] = r; g_valC[pC] = val;
}

// ---------------- fused dual GEMM ----------------
// Block: 256 threads, 64-node tile, 192 output "cols" (96 xs + 96 xt).
// Thread microtile: 8 nodes x 6 interleaved cols (col = tcol + 32*m).
#define GT   256
#define NT   64
#define XPAD 100          // floats per smem row (f4-aligned, conflict-free LDS.128)
#define XPAD4 25

__global__ void __launch_bounds__(GT, 2)
gemm_kernel(const float* __restrict__ x,
            const float* __restrict__ Wsd,
            const float* __restrict__ Wds,
            int N) {
    extern __shared__ float sm[];
    float* Wc = sm;                  // [192][XPAD]
    float* Xs = sm + 192 * XPAD;     // [NT][XPAD]

    int tid = threadIdx.x;

    const float4* Wsd4 = (const float4*)Wsd;   // 96*24
    const float4* Wds4 = (const float4*)Wds;
    for (int i = tid; i < 96 * D4; i += GT) {
        int j = i / D4, kk = i % D4;
        float4 a = Wsd4[i];
        float4 b = Wds4[i];
        ((float4*)&Wc[j * XPAD])[kk] =
            make_float4(ALPHA * a.x, ALPHA * a.y, ALPHA * a.z, ALPHA * a.w);
        ((float4*)&Wc[(j + 96) * XPAD])[kk] =
            make_float4((1.0f - ALPHA) * b.x, (1.0f - ALPHA) * b.y,
                        (1.0f - ALPHA) * b.z, (1.0f - ALPHA) * b.w);
    }
    int nb = blockIdx.x * NT;
    const float4* x4 = (const float4*)x;
    for (int i = tid; i < NT * D4; i += GT) {
        int r = i / D4, kk = i % D4;
        int n = nb + r;
        ((float4*)&Xs[r * XPAD])[kk] =
            (n < N) ? x4[n * D4 + kk] : make_float4(0.f, 0.f, 0.f, 0.f);
    }
    __syncthreads();

    int tcol  = tid & 31;     // cols tcol + 32*m, m=0..5
    int tnode = tid >> 5;     // nodes tnode*8 .. +7  (uniform per warp -> X broadcast)

    float acc[8][6];
#pragma unroll
    for (int i = 0; i < 8; i++)
#pragma unroll
        for (int c = 0; c < 6; c++) acc[i][c] = 0.0f;

    const float4* Xb = (const float4*)&Xs[(tnode * 8) * XPAD];
    const float4* Wb = (const float4*)&Wc[tcol * XPAD];

#pragma unroll 2
    for (int kk = 0; kk < D4; kk++) {
        float4 wv[6];
#pragma unroll
        for (int m = 0; m < 6; m++) wv[m] = Wb[m * 32 * XPAD4 + kk];
#pragma unroll
        for (int i = 0; i < 8; i++) {
            float4 xv = Xb[i * XPAD4 + kk];
#pragma unroll
            for (int m = 0; m < 6; m++) {
                acc[i][m] += xv.x * wv[m].x;
                acc[i][m] += xv.y * wv[m].y;
                acc[i][m] += xv.z * wv[m].z;
                acc[i][m] += xv.w * wv[m].w;
            }
        }
    }

    // coalesced epilogue: lane tcol writes col tcol+32m
#pragma unroll
    for (int i = 0; i < 8; i++) {
        int n = nb + tnode * 8 + i;
        if (n >= N) continue;
#pragma unroll
        for (int m = 0; m < 6; m++) {
            int col = tcol + 32 * m;
            if (col < D) g_xs[n * D + col]       = acc[i][m];
            else         g_xt[n * D + (col - D)] = acc[i][m];
        }
    }
}

// ---------------- fused gather (both directions + bias) ----------------
// One warp per node; lanes 0..23 each own one float4 chunk of the 96-dim row.

__global__ void gather_kernel(float* __restrict__ out,
                              const float* __restrict__ b_sd,
                              const float* __restrict__ b_ds,
                              int N) {
    int warp = (blockIdx.x * blockDim.x + threadIdx.x) >> 5;
    int lane = threadIdx.x & 31;
    if (warp >= N || lane >= D4) return;
    int n = warp;

    const float4* xs4 = (const float4*)g_xs;
    const float4* xt4 = (const float4*)g_xt;

    float4 accS = make_float4(0.f, 0.f, 0.f, 0.f);
    float4 accT = make_float4(0.f, 0.f, 0.f, 0.f);

    // direction 1: out[n] += sum val(e) * xs[col]  over out-edges of n
    {
        int s = g_startR[n];
        int d = g_odeg[n];
        int j = 0;
        for (; j + 4 <= d; j += 4) {
            int   i0 = g_idxR[s + j],     i1 = g_idxR[s + j + 1];
            int   i2 = g_idxR[s + j + 2], i3 = g_idxR[s + j + 3];
            float v0 = g_valR[s + j],     v1 = g_valR[s + j + 1];
            float v2 = g_valR[s + j + 2], v3 = g_valR[s + j + 3];
            float4 m0 = xs4[i0 * D4 + lane];
            float4 m1 = xs4[i1 * D4 + lane];
            float4 m2 = xs4[i2 * D4 + lane];
            float4 m3 = xs4[i3 * D4 + lane];
            accS.x += v0 * m0.x + v1 * m1.x + v2 * m2.x + v3 * m3.x;
            accS.y += v0 * m0.y + v1 * m1.y + v2 * m2.y + v3 * m3.y;
            accS.z += v0 * m0.z + v1 * m1.z + v2 * m2.z + v3 * m3.z;
            accS.w += v0 * m0.w + v1 * m1.w + v2 * m2.w + v3 * m3.w;
        }
        for (; j < d; j++) {
            int   i0 = g_idxR[s + j];
            float v0 = g_valR[s + j];
            float4 m0 = xs4[i0 * D4 + lane];
            accS.x += v0 * m0.x; accS.y += v0 * m0.y;
            accS.z += v0 * m0.z; accS.w += v0 * m0.w;
        }
    }
    // direction 2: out[n] += sum val(e) * xt[row]  over in-edges of n
    {
        int s = g_startC[n];
        int d = g_ideg[n];
        int j = 0;
        for (; j + 4 <= d; j += 4) {
            int   i0 = g_idxC[s + j],     i1 = g_idxC[s + j + 1];
            int   i2 = g_idxC[s + j + 2], i3 = g_idxC[s + j + 3];
            float v0 = g_valC[s + j],     v1 = g_valC[s + j + 1];
            float v2 = g_valC[s + j + 2], v3 = g_valC[s + j + 3];
            float4 m0 = xt4[i0 * D4 + lane];
            float4 m1 = xt4[i1 * D4 + lane];
            float4 m2 = xt4[i2 * D4 + lane];
            float4 m3 = xt4[i3 * D4 + lane];
            accT.x += v0 * m0.x + v1 * m1.x + v2 * m2.x + v3 * m3.x;
            accT.y += v0 * m0.y + v1 * m1.y + v2 * m2.y + v3 * m3.y;
            accT.z += v0 * m0.z + v1 * m1.z + v2 * m2.z + v3 * m3.z;
            accT.w += v0 * m0.w + v1 * m1.w + v2 * m2.w + v3 * m3.w;
        }
        for (; j < d; j++) {
            int   i0 = g_idxC[s + j];
            float v0 = g_valC[s + j];
            float4 m0 = xt4[i0 * D4 + lane];
            accT.x += v0 * m0.x; accT.y += v0 * m0.y;
            accT.z += v0 * m0.z; accT.w += v0 * m0.w;
        }
    }

    float4 bs = ((const float4*)b_sd)[lane];
    float4 bd = ((const float4*)b_ds)[lane];
    float4 o;
    o.x = accS.x + accT.x + ALPHA * bs.x + (1.0f - ALPHA) * bd.x;
    o.y = accS.y + accT.y + ALPHA * bs.y + (1.0f - ALPHA) * bd.y;
    o.z = accS.z + accT.z + ALPHA * bs.z + (1.0f - ALPHA) * bd.z;
    o.w = accS.w + accT.w + ALPHA * bs.w + (1.0f - ALPHA) * bd.w;
    ((float4*)out)[n * D4 + lane] = o;
}

// ---------------- launch ----------------

extern "C" void kernel_launch(void* const* d_in, const int* in_sizes, int n_in,
                              void* d_out, int out_size) {
    const float* x    = (const float*)d_in[0];
    const float* Wsd  = (const float*)d_in[1];
    const float* b_sd = (const float*)d_in[2];
    const float* Wds  = (const float*)d_in[3];
    const float* b_ds = (const float*)d_in[4];
    const int*   ei   = (const int*)  d_in[5];
    float* out = (float*)d_out;

    int N = in_sizes[0] / D;
    int E = in_sizes[5] / 2;

    size_t smem = (size_t)(192 + NT) * XPAD * sizeof(float);
    cudaFuncSetAttribute(gemm_kernel, cudaFuncAttributeMaxDynamicSharedMemorySize,
                         (int)smem);

    int nScan = (N + 255) / 256;

    zero_kernel <<<(N + 255) / 256, 256>>>(N);
    deg_kernel  <<<(E + 255) / 256, 256>>>(ei, E);
    rsqrt_kernel<<<(N + 255) / 256, 256>>>(N);
    scan1_kernel<<<nScan, 256>>>(N);
    scan2_kernel<<<1, 256>>>(nScan);
    scan3_kernel<<<(N + 255) / 256, 256>>>(N);
    build_kernel<<<(E + 255) / 256, 256>>>(ei, E);
    gemm_kernel <<<(N + NT - 1) / NT, GT, smem>>>(x, Wsd, Wds, N);
    // one warp per node
    long long gthreads = (long long)N * 32;
    gather_kernel<<<(int)((gthreads + 255) / 256), 256>>>(out, b_sd, b_ds, N);
}

// round 4
// speedup vs baseline: 1.6569x; 1.1795x over previous
#include <cuda_runtime.h>
#include <cuda_fp16.h>

// DirGCNConv restructured:
//   xs = x @ (a*Wsd)^T ; xt = x @ ((1-a)*Wds)^T   (fused dual GEMM, fp16 output)
//   CSR (by row) + CSC (by col) via counting sort; (idx,val) interleaved pairs
//   out[n] = bias + sum_{e:row=n} val*xs[col] + sum_{e:col=n} val*xt[row]
// fp32 accumulation everywhere; fp16 only as message storage format.

#define MAXN 50048
#define MAXE 810000
#define D    96
#define D4   24
#define ALPHA 0.5f

// -------- static scratch --------
__device__ int   g_odeg [MAXN];
__device__ int   g_ideg [MAXN];
__device__ int   g_startR[MAXN];
__device__ int   g_startC[MAXN];
__device__ int   g_curR [MAXN];
__device__ int   g_curC [MAXN];
__device__ int   g_bsumR[256];
__device__ int   g_bsumC[256];
__device__ int   g_boffR[256];
__device__ int   g_boffC[256];
__device__ int2  g_pairR[MAXE];     // (neighbor idx, val as bits)
__device__ int2  g_pairC[MAXE];
__device__ __align__(16) __half g_xs[MAXN * D];
__device__ __align__(16) __half g_xt[MAXN * D];

// ---------------- degree ----------------

__global__ void zero_kernel(int N) {
    int i = blockIdx.x * blockDim.x + threadIdx.x;
    if (i < N) { g_odeg[i] = 0; g_ideg[i] = 0; }
}

__global__ void deg_kernel(const int* __restrict__ ei, int E) {
    int e = blockIdx.x * blockDim.x + threadIdx.x;
    if (e >= E) return;
    atomicAdd(&g_odeg[ei[e]],     1);
    atomicAdd(&g_ideg[ei[E + e]], 1);
}

// ---------------- prefix scan (warp-shuffle) ----------------

__device__ __forceinline__ int warp_incl_scan(int v) {
#pragma unroll
    for (int off = 1; off < 32; off <<= 1) {
        int a = __shfl_up_sync(0xffffffffu, v, off);
        if ((threadIdx.x & 31) >= off) v += a;
    }
    return v;
}

__global__ void scan1_kernel(int N) {
    __shared__ int wR[8], wC[8];
    int t = threadIdx.x, lane = t & 31, wid = t >> 5;
    int i = blockIdx.x * 256 + t;
    int vR = (i < N) ? g_odeg[i] : 0;
    int vC = (i < N) ? g_ideg[i] : 0;
    int sR = warp_incl_scan(vR);
    int sC = warp_incl_scan(vC);
    if (lane == 31) { wR[wid] = sR; wC[wid] = sC; }
    __syncthreads();
    if (wid == 0) {
        int aR = (lane < 8) ? wR[lane] : 0;
        int aC = (lane < 8) ? wC[lane] : 0;
        aR = warp_incl_scan(aR);
        aC = warp_incl_scan(aC);
        if (lane < 8) { wR[lane] = aR; wC[lane] = aC; }
    }
    __syncthreads();
    int offR = (wid > 0) ? wR[wid - 1] : 0;
    int offC = (wid > 0) ? wC[wid - 1] : 0;
    if (i < N) {
        g_startR[i] = offR + sR - vR;
        g_startC[i] = offC + sC - vC;
    }
    if (t == 255) { g_bsumR[blockIdx.x] = offR + sR; g_bsumC[blockIdx.x] = offC + sC; }
}

__global__ void scan2_kernel(int nblocks) {
    __shared__ int wR[8], wC[8];
    int t = threadIdx.x, lane = t & 31, wid = t >> 5;
    int vR = (t < nblocks) ? g_bsumR[t] : 0;
    int vC = (t < nblocks) ? g_bsumC[t] : 0;
    int sR = warp_incl_scan(vR);
    int sC = warp_incl_scan(vC);
    if (lane == 31) { wR[wid] = sR; wC[wid] = sC; }
    __syncthreads();
    if (wid == 0) {
        int aR = (lane < 8) ? wR[lane] : 0;
        int aC = (lane < 8) ? wC[lane] : 0;
        aR = warp_incl_scan(aR);
        aC = warp_incl_scan(aC);
        if (lane < 8) { wR[lane] = aR; wC[lane] = aC; }
    }
    __syncthreads();
    int offR = (wid > 0) ? wR[wid - 1] : 0;
    int offC = (wid > 0) ? wC[wid - 1] : 0;
    if (t < nblocks) { g_boffR[t] = offR + sR - vR; g_boffC[t] = offC + sC - vC; }
}

__global__ void scan3_kernel(int N) {
    int i = blockIdx.x * blockDim.x + threadIdx.x;
    if (i >= N) return;
    int b = i >> 8;
    int sR = g_startR[i] + g_boffR[b];
    int sC = g_startC[i] + g_boffC[b];
    g_startR[i] = sR; g_curR[i] = sR;
    g_startC[i] = sC; g_curC[i] = sC;
}

// ---------------- CSR/CSC build (rsqrt fused; endpoints always have deg>=1) ---

__global__ void build_kernel(const int* __restrict__ ei, int E) {
    int e = blockIdx.x * blockDim.x + threadIdx.x;
    if (e >= E) return;
    int r = ei[e];
    int c = ei[E + e];
    float val = rsqrtf((float)g_odeg[r]) * rsqrtf((float)g_ideg[c]);
    int vb = __float_as_int(val);
    int pR = atomicAdd(&g_curR[r], 1);
    g_pairR[pR] = make_int2(c, vb);
    int pC = atomicAdd(&g_curC[c], 1);
    g_pairC[pC] = make_int2(r, vb);
}

// ---------------- fused dual GEMM (fp16 output) ----------------
#define GT   256
#define NT   64
#define XPAD 100
#define XPAD4 25

__global__ void __launch_bounds__(GT, 2)
gemm_kernel(const float* __restrict__ x,
            const float* __restrict__ Wsd,
            const float* __restrict__ Wds,
            int N) {
    extern __shared__ float sm[];
    float* Wc = sm;                  // [192][XPAD]
    float* Xs = sm + 192 * XPAD;     // [NT][XPAD]

    int tid = threadIdx.x;

    const float4* Wsd4 = (const float4*)Wsd;
    const float4* Wds4 = (const float4*)Wds;
    for (int i = tid; i < 96 * D4; i += GT) {
        int j = i / D4, kk = i % D4;
        float4 a = Wsd4[i];
        float4 b = Wds4[i];
        ((float4*)&Wc[j * XPAD])[kk] =
            make_float4(ALPHA * a.x, ALPHA * a.y, ALPHA * a.z, ALPHA * a.w);
        ((float4*)&Wc[(j + 96) * XPAD])[kk] =
            make_float4((1.0f - ALPHA) * b.x, (1.0f - ALPHA) * b.y,
                        (1.0f - ALPHA) * b.z, (1.0f - ALPHA) * b.w);
    }
    int nb = blockIdx.x * NT;
    const float4* x4 = (const float4*)x;
    for (int i = tid; i < NT * D4; i += GT) {
        int r = i / D4, kk = i % D4;
        int n = nb + r;
        ((float4*)&Xs[r * XPAD])[kk] =
            (n < N) ? x4[n * D4 + kk] : make_float4(0.f, 0.f, 0.f, 0.f);
    }
    __syncthreads();

    int tcol  = tid & 31;     // cols tcol + 32*m
    int tnode = tid >> 5;     // nodes tnode*8 .. +7

    float acc[8][6];
#pragma unroll
    for (int i = 0; i < 8; i++)
#pragma unroll
        for (int c = 0; c < 6; c++) acc[i][c] = 0.0f;

    const float4* Xb = (const float4*)&Xs[(tnode * 8) * XPAD];
    const float4* Wb = (const float4*)&Wc[tcol * XPAD];

#pragma unroll 2
    for (int kk = 0; kk < D4; kk++) {
        float4 wv[6];
#pragma unroll
        for (int m = 0; m < 6; m++) wv[m] = Wb[m * 32 * XPAD4 + kk];
#pragma unroll
        for (int i = 0; i < 8; i++) {
            float4 xv = Xb[i * XPAD4 + kk];
#pragma unroll
            for (int m = 0; m < 6; m++) {
                acc[i][m] += xv.x * wv[m].x;
                acc[i][m] += xv.y * wv[m].y;
                acc[i][m] += xv.z * wv[m].z;
                acc[i][m] += xv.w * wv[m].w;
            }
        }
    }

#pragma unroll
    for (int i = 0; i < 8; i++) {
        int n = nb + tnode * 8 + i;
        if (n >= N) continue;
#pragma unroll
        for (int m = 0; m < 6; m++) {
            int col = tcol + 32 * m;
            if (col < D) g_xs[n * D + col]       = __float2half_rn(acc[i][m]);
            else         g_xt[n * D + (col - D)] = __float2half_rn(acc[i][m]);
        }
    }
}

// ---------------- fused gather ----------------
// One warp per node; lanes 0..23 each own 4 features (one uint2 = 2 half2).

__device__ __forceinline__ void acc_msg(float4& acc, float v, uint2 u) {
    float2 a = __half22float2(*(__half2*)&u.x);
    float2 b = __half22float2(*(__half2*)&u.y);
    acc.x += v * a.x; acc.y += v * a.y;
    acc.z += v * b.x; acc.w += v * b.y;
}

__global__ void gather_kernel(float* __restrict__ out,
                              const float* __restrict__ b_sd,
                              const float* __restrict__ b_ds,
                              int N) {
    int warp = (blockIdx.x * blockDim.x + threadIdx.x) >> 5;
    int lane = threadIdx.x & 31;
    if (warp >= N || lane >= D4) return;
    int n = warp;

    const uint2* xs2 = (const uint2*)g_xs;   // 24 uint2 per row
    const uint2* xt2 = (const uint2*)g_xt;

    float4 acc = make_float4(0.f, 0.f, 0.f, 0.f);

    {
        int s = g_startR[n];
        int d = g_odeg[n];
        int j = 0;
        for (; j + 4 <= d; j += 4) {
            int2 p0 = g_pairR[s + j],     p1 = g_pairR[s + j + 1];
            int2 p2 = g_pairR[s + j + 2], p3 = g_pairR[s + j + 3];
            uint2 m0 = xs2[p0.x * D4 + lane];
            uint2 m1 = xs2[p1.x * D4 + lane];
            uint2 m2 = xs2[p2.x * D4 + lane];
            uint2 m3 = xs2[p3.x * D4 + lane];
            acc_msg(acc, __int_as_float(p0.y), m0);
            acc_msg(acc, __int_as_float(p1.y), m1);
            acc_msg(acc, __int_as_float(p2.y), m2);
            acc_msg(acc, __int_as_float(p3.y), m3);
        }
        for (; j < d; j++) {
            int2 p0 = g_pairR[s + j];
            acc_msg(acc, __int_as_float(p0.y), xs2[p0.x * D4 + lane]);
        }
    }
    {
        int s = g_startC[n];
        int d = g_ideg[n];
        int j = 0;
        for (; j + 4 <= d; j += 4) {
            int2 p0 = g_pairC[s + j],     p1 = g_pairC[s + j + 1];
            int2 p2 = g_pairC[s + j + 2], p3 = g_pairC[s + j + 3];
            uint2 m0 = xt2[p0.x * D4 + lane];
            uint2 m1 = xt2[p1.x * D4 + lane];
            uint2 m2 = xt2[p2.x * D4 + lane];
            uint2 m3 = xt2[p3.x * D4 + lane];
            acc_msg(acc, __int_as_float(p0.y), m0);
            acc_msg(acc, __int_as_float(p1.y), m1);
            acc_msg(acc, __int_as_float(p2.y), m2);
            acc_msg(acc, __int_as_float(p3.y), m3);
        }
        for (; j < d; j++) {
            int2 p0 = g_pairC[s + j];
            acc_msg(acc, __int_as_float(p0.y), xt2[p0.x * D4 + lane]);
        }
    }

    float4 bs = ((const float4*)b_sd)[lane];
    float4 bd = ((const float4*)b_ds)[lane];
    float4 o;
    o.x = acc.x + ALPHA * bs.x + (1.0f - ALPHA) * bd.x;
    o.y = acc.y + ALPHA * bs.y + (1.0f - ALPHA) * bd.y;
    o.z = acc.z + ALPHA * bs.z + (1.0f - ALPHA) * bd.z;
    o.w = acc.w + ALPHA * bs.w + (1.0f - ALPHA) * bd.w;
    ((float4*)out)[n * D4 + lane] = o;
}

// ---------------- launch ----------------

extern "C" void kernel_launch(void* const* d_in, const int* in_sizes, int n_in,
                              void* d_out, int out_size) {
    const float* x    = (const float*)d_in[0];
    const float* Wsd  = (const float*)d_in[1];
    const float* b_sd = (const float*)d_in[2];
    const float* Wds  = (const float*)d_in[3];
    const float* b_ds = (const float*)d_in[4];
    const int*   ei   = (const int*)  d_in[5];
    float* out = (float*)d_out;

    int N = in_sizes[0] / D;
    int E = in_sizes[5] / 2;

    size_t smem = (size_t)(192 + NT) * XPAD * sizeof(float);
    cudaFuncSetAttribute(gemm_kernel, cudaFuncAttributeMaxDynamicSharedMemorySize,
                         (int)smem);

    int nScan = (N + 255) / 256;

    zero_kernel <<<(N + 255) / 256, 256>>>(N);
    deg_kernel  <<<(E + 255) / 256, 256>>>(ei, E);
    scan1_kernel<<<nScan, 256>>>(N);
    scan2_kernel<<<1, 256>>>(nScan);
    scan3_kernel<<<(N + 255) / 256, 256>>>(N);
    build_kernel<<<(E + 255) / 256, 256>>>(ei, E);
    gemm_kernel <<<(N + NT - 1) / NT, GT, smem>>>(x, Wsd, Wds, N);
    long long gthreads = (long long)N * 32;
    gather_kernel<<<(int)((gthreads + 255) / 256), 256>>>(out, b_sd, b_ds, N);
}

// round 6
// speedup vs baseline: 2.2264x; 1.3437x over previous
#include <cuda_runtime.h>
#include <cuda_fp16.h>
#include <cstdint>

// DirGCNConv:
//   xs = x @ (a*Wsd)^T ; xt = x @ ((1-a)*Wds)^T    (HMMA fp16 GEMM, fp32 acc)
//   CSR/CSC via counting sort; gather accumulates fp32, writes out once.

typedef unsigned int u32;

#define MAXN 50048
#define MAXE 810000
#define D    96
#define D4   24
#define ALPHA 0.5f

// -------- static scratch --------
__device__ int   g_odeg [MAXN];
__device__ int   g_ideg [MAXN];
__device__ int   g_startR[MAXN];
__device__ int   g_startC[MAXN];
__device__ int   g_curR [MAXN];
__device__ int   g_curC [MAXN];
__device__ int   g_bsumR[256];
__device__ int   g_bsumC[256];
__device__ int2  g_pairR[MAXE];
__device__ int2  g_pairC[MAXE];
__device__ __align__(16) __half g_wh[192 * D];   // pre-scaled fp16 weights
__device__ __align__(16) __half g_xs[MAXN * D];
__device__ __align__(16) __half g_xt[MAXN * D];

// ---------------- mma helpers ----------------

__device__ __forceinline__ u32 s2u(const void* p) {
    return (u32)__cvta_generic_to_shared(p);
}

__device__ __forceinline__ void ldsm4(u32& r0, u32& r1, u32& r2, u32& r3, u32 addr) {
    asm volatile("ldmatrix.sync.aligned.m8n8.x4.shared.b16 {%0,%1,%2,%3}, [%4];"
                 : "=r"(r0), "=r"(r1), "=r"(r2), "=r"(r3) : "r"(addr));
}

__device__ __forceinline__ void mma16816(float& c0, float& c1, float& c2, float& c3,
                                         const u32* a, const u32* b) {
    asm volatile(
        "mma.sync.aligned.m16n8k16.row.col.f32.f16.f16.f32 "
        "{%0,%1,%2,%3}, {%4,%5,%6,%7}, {%8,%9}, {%0,%1,%2,%3};"
        : "+f"(c0), "+f"(c1), "+f"(c2), "+f"(c3)
        : "r"(a[0]), "r"(a[1]), "r"(a[2]), "r"(a[3]), "r"(b[0]), "r"(b[1]));
}

// ---------------- degree ----------------

__global__ void zero_kernel(int N) {
    int i = blockIdx.x * blockDim.x + threadIdx.x;
    if (i < N) { g_odeg[i] = 0; g_ideg[i] = 0; }
}

__global__ void deg_kernel(const int* __restrict__ ei, int E) {
    int e = blockIdx.x * blockDim.x + threadIdx.x;
    if (e >= E) return;
    atomicAdd(&g_odeg[ei[e]],     1);
    atomicAdd(&g_ideg[ei[E + e]], 1);
}

// ---------------- prefix scans ----------------

__device__ __forceinline__ int warp_incl_scan(int v) {
#pragma unroll
    for (int off = 1; off < 32; off <<= 1) {
        int a = __shfl_up_sync(0xffffffffu, v, off);
        if ((threadIdx.x & 31) >= off) v += a;
    }
    return v;
}

__global__ void scan1_kernel(int N) {
    __shared__ int wR[8], wC[8];
    int t = threadIdx.x, lane = t & 31, wid = t >> 5;
    int i = blockIdx.x * 256 + t;
    int vR = (i < N) ? g_odeg[i] : 0;
    int vC = (i < N) ? g_ideg[i] : 0;
    int sR = warp_incl_scan(vR);
    int sC = warp_incl_scan(vC);
    if (lane == 31) { wR[wid] = sR; wC[wid] = sC; }
    __syncthreads();
    if (wid == 0) {
        int aR = (lane < 8) ? wR[lane] : 0;
        int aC = (lane < 8) ? wC[lane] : 0;
        aR = warp_incl_scan(aR);
        aC = warp_incl_scan(aC);
        if (lane < 8) { wR[lane] = aR; wC[lane] = aC; }
    }
    __syncthreads();
    int offR = (wid > 0) ? wR[wid - 1] : 0;
    int offC = (wid > 0) ? wC[wid - 1] : 0;
    if (i < N) {
        g_startR[i] = offR + sR - vR;
        g_startC[i] = offC + sC - vC;
    }
    if (t == 255) { g_bsumR[blockIdx.x] = offR + sR; g_bsumC[blockIdx.x] = offC + sC; }
}

// fused scan2+scan3: every block re-scans the (<=256) block sums, picks its own
// offset, then applies it to its 256-element range.
__global__ void scan23_kernel(int N, int nblocks) {
    __shared__ int wR[8], wC[8];
    __shared__ int offRs, offCs;
    int t = threadIdx.x, lane = t & 31, wid = t >> 5;
    int vR = (t < nblocks) ? g_bsumR[t] : 0;
    int vC = (t < nblocks) ? g_bsumC[t] : 0;
    int sR = warp_incl_scan(vR);
    int sC = warp_incl_scan(vC);
    if (lane == 31) { wR[wid] = sR; wC[wid] = sC; }
    __syncthreads();
    if (wid == 0) {
        int aR = (lane < 8) ? wR[lane] : 0;
        int aC = (lane < 8) ? wC[lane] : 0;
        aR = warp_incl_scan(aR);
        aC = warp_incl_scan(aC);
        if (lane < 8) { wR[lane] = aR; wC[lane] = aC; }
    }
    __syncthreads();
    if (t == (int)blockIdx.x) {
        int woffR = (wid > 0) ? wR[wid - 1] : 0;
        int woffC = (wid > 0) ? wC[wid - 1] : 0;
        offRs = woffR + sR - vR;
        offCs = woffC + sC - vC;
    }
    __syncthreads();
    int i = blockIdx.x * 256 + t;
    if (i < N) {
        int aR = g_startR[i] + offRs;
        int aC = g_startC[i] + offCs;
        g_startR[i] = aR; g_curR[i] = aR;
        g_startC[i] = aC; g_curC[i] = aC;
    }
}

// ---------------- CSR/CSC build ----------------

__global__ void build_kernel(const int* __restrict__ ei, int E) {
    int e = blockIdx.x * blockDim.x + threadIdx.x;
    if (e >= E) return;
    int r = ei[e];
    int c = ei[E + e];
    float val = rsqrtf((float)g_odeg[r]) * rsqrtf((float)g_ideg[c]);
    int vb = __float_as_int(val);
    int pR = atomicAdd(&g_curR[r], 1);
    g_pairR[pR] = make_int2(c, vb);
    int pC = atomicAdd(&g_curC[c], 1);
    g_pairC[pC] = make_int2(r, vb);
}

// ---------------- weight prep: fp16, pre-scaled ----------------

__global__ void wprep_kernel(const float* __restrict__ Wsd,
                             const float* __restrict__ Wds) {
    int i = blockIdx.x * blockDim.x + threadIdx.x;
    if (i >= D * D) return;
    g_wh[i]         = __float2half_rn(ALPHA          * Wsd[i]);   // rows 0..95
    g_wh[D * D + i] = __float2half_rn((1.0f - ALPHA) * Wds[i]);   // rows 96..191
}

// ---------------- HMMA GEMM ----------------
// Block: 256 threads (8 warps), 128-node tile x 192 cols.
// Warp: one m16 tile, 24 n8 tiles, K=96 (6 k16 steps).
#define LDH 104   // padded halfs per smem row (208B stride: 8-row ldmatrix conflict-free)

__global__ void __launch_bounds__(256)
gemm_mma_kernel(const float* __restrict__ x, int N) {
    extern __shared__ __half sh[];
    __half* Xs = sh;               // [128][LDH]
    __half* Ws = sh + 128 * LDH;   // [192][LDH]

    int tid = threadIdx.x;
    int nb  = blockIdx.x * 128;

    // stage W (fp16 half2 copies)
    const u32* w2 = (const u32*)g_wh;       // 192*48 half2
    for (int i = tid; i < 192 * 48; i += 256) {
        int r = i / 48, c = i % 48;
        *(u32*)&Ws[r * LDH + c * 2] = w2[i];
    }
    // stage X tile: f32 -> fp16
    const float4* x4 = (const float4*)x;
    for (int i = tid; i < 128 * D4; i += 256) {
        int r = i / D4, c = i % D4;
        int n = nb + r;
        float4 v = (n < N) ? x4[n * D4 + c] : make_float4(0.f, 0.f, 0.f, 0.f);
        *(__half2*)&Xs[r * LDH + c * 4]     = __floats2half2_rn(v.x, v.y);
        *(__half2*)&Xs[r * LDH + c * 4 + 2] = __floats2half2_rn(v.z, v.w);
    }
    __syncthreads();

    int wid = tid >> 5, l = tid & 31;
    int mrow = wid * 16;

    // A fragments: 6 k-steps, each via ldmatrix.x4
    u32 a[6][4];
    u32 a_addr0 = s2u(&Xs[(mrow + (l & 15)) * LDH + (l >> 4) * 8]);
#pragma unroll
    for (int s = 0; s < 6; s++)
        ldsm4(a[s][0], a[s][1], a[s][2], a[s][3], a_addr0 + s * 32);

    // B lane base: row (l&7) within n-tile, k-chunk group (l>>3)
    u32 b_addr0 = s2u(&Ws[(l & 7) * LDH + (l >> 3) * 8]);

    int r0n = nb + mrow + (l >> 2);   // store rows: r0n and r0n+8
    int ccol = 2 * (l & 3);

#pragma unroll
    for (int nt = 0; nt < 24; nt++) {
        float c0 = 0.f, c1 = 0.f, c2 = 0.f, c3 = 0.f;
        u32 b[6][2];
#pragma unroll
        for (int j = 0; j < 3; j++) {
            u32 r0, r1, r2, r3;
            ldsm4(r0, r1, r2, r3, b_addr0 + nt * 8 * LDH * 2 + j * 64);
            b[2 * j][0] = r0; b[2 * j][1] = r1;
            b[2 * j + 1][0] = r2; b[2 * j + 1][1] = r3;
        }
#pragma unroll
        for (int s = 0; s < 6; s++)
            mma16816(c0, c1, c2, c3, a[s], b[s]);

        int c = nt * 8 + ccol;
        __half* dst = (c < D) ? g_xs : g_xt;
        int cc = (c < D) ? c : c - D;
        if (r0n < N)
            *(__half2*)&dst[r0n * D + cc] = __floats2half2_rn(c0, c1);
        if (r0n + 8 < N)
            *(__half2*)&dst[(r0n + 8) * D + cc] = __floats2half2_rn(c2, c3);
    }
}

// ---------------- fused gather ----------------

__device__ __forceinline__ void acc_msg(float4& acc, float v, uint2 u) {
    float2 a = __half22float2(*(__half2*)&u.x);
    float2 b = __half22float2(*(__half2*)&u.y);
    acc.x += v * a.x; acc.y += v * a.y;
    acc.z += v * b.x; acc.w += v * b.y;
}

__global__ void gather_kernel(float* __restrict__ out,
                              const float* __restrict__ b_sd,
                              const float* __restrict__ b_ds,
                              int N) {
    int warp = (blockIdx.x * blockDim.x + threadIdx.x) >> 5;
    int lane = threadIdx.x & 31;
    if (warp >= N || lane >= D4) return;
    int n = warp;

    const uint2* xs2 = (const uint2*)g_xs;
    const uint2* xt2 = (const uint2*)g_xt;

    float4 acc = make_float4(0.f, 0.f, 0.f, 0.f);

    {
        int s = g_startR[n];
        int d = g_odeg[n];
        int j = 0;
        for (; j + 4 <= d; j += 4) {
            int2 p0 = g_pairR[s + j],     p1 = g_pairR[s + j + 1];
            int2 p2 = g_pairR[s + j + 2], p3 = g_pairR[s + j + 3];
            uint2 m0 = xs2[p0.x * D4 + lane];
            uint2 m1 = xs2[p1.x * D4 + lane];
            uint2 m2 = xs2[p2.x * D4 + lane];
            uint2 m3 = xs2[p3.x * D4 + lane];
            acc_msg(acc, __int_as_float(p0.y), m0);
            acc_msg(acc, __int_as_float(p1.y), m1);
            acc_msg(acc, __int_as_float(p2.y), m2);
            acc_msg(acc, __int_as_float(p3.y), m3);
        }
        for (; j < d; j++) {
            int2 p0 = g_pairR[s + j];
            acc_msg(acc, __int_as_float(p0.y), xs2[p0.x * D4 + lane]);
        }
    }
    {
        int s = g_startC[n];
        int d = g_ideg[n];
        int j = 0;
        for (; j + 4 <= d; j += 4) {
            int2 p0 = g_pairC[s + j],     p1 = g_pairC[s + j + 1];
            int2 p2 = g_pairC[s + j + 2], p3 = g_pairC[s + j + 3];
            uint2 m0 = xt2[p0.x * D4 + lane];
            uint2 m1 = xt2[p1.x * D4 + lane];
            uint2 m2 = xt2[p2.x * D4 + lane];
            uint2 m3 = xt2[p3.x * D4 + lane];
            acc_msg(acc, __int_as_float(p0.y), m0);
            acc_msg(acc, __int_as_float(p1.y), m1);
            acc_msg(acc, __int_as_float(p2.y), m2);
            acc_msg(acc, __int_as_float(p3.y), m3);
        }
        for (; j < d; j++) {
            int2 p0 = g_pairC[s + j];
            acc_msg(acc, __int_as_float(p0.y), xt2[p0.x * D4 + lane]);
        }
    }

    float4 bs = ((const float4*)b_sd)[lane];
    float4 bd = ((const float4*)b_ds)[lane];
    float4 o;
    o.x = acc.x + ALPHA * bs.x + (1.0f - ALPHA) * bd.x;
    o.y = acc.y + ALPHA * bs.y + (1.0f - ALPHA) * bd.y;
    o.z = acc.z + ALPHA * bs.z + (1.0f - ALPHA) * bd.z;
    o.w = acc.w + ALPHA * bs.w + (1.0f - ALPHA) * bd.w;
    ((float4*)out)[n * D4 + lane] = o;
}

// ---------------- launch ----------------

extern "C" void kernel_launch(void* const* d_in, const int* in_sizes, int n_in,
                              void* d_out, int out_size) {
    const float* x    = (const float*)d_in[0];
    const float* Wsd  = (const float*)d_in[1];
    const float* b_sd = (const float*)d_in[2];
    const float* Wds  = (const float*)d_in[3];
    const float* b_ds = (const float*)d_in[4];
    const int*   ei   = (const int*)  d_in[5];
    float* out = (float*)d_out;

    int N = in_sizes[0] / D;
    int E = in_sizes[5] / 2;

    size_t smem = (size_t)(128 + 192) * LDH * sizeof(__half);   // 66560 B
    cudaFuncSetAttribute(gemm_mma_kernel,
                         cudaFuncAttributeMaxDynamicSharedMemorySize, (int)smem);

    int nScan = (N + 255) / 256;

    wprep_kernel <<<(D * D + 255) / 256, 256>>>(Wsd, Wds);
    zero_kernel  <<<(N + 255) / 256, 256>>>(N);
    deg_kernel   <<<(E + 255) / 256, 256>>>(ei, E);
    scan1_kernel <<<nScan, 256>>>(N);
    scan23_kernel<<<nScan, 256>>>(N, nScan);
    build_kernel <<<(E + 255) / 256, 256>>>(ei, E);
    gemm_mma_kernel<<<(N + 127) / 128, 256, smem>>>(x, N);
    long long gthreads = (long long)N * 32;
    gather_kernel<<<(int)((gthreads + 255) / 256), 256>>>(out, b_sd, b_ds, N);
}

// round 7
// speedup vs baseline: 2.3130x; 1.0389x over previous
#include <cuda_runtime.h>
#include <cuda_fp16.h>
#include <cstdint>

// DirGCNConv:
//   xs = x @ (a*Wsd)^T ; xt = x @ ((1-a)*Wds)^T    (HMMA fp16 GEMM, fp32 acc)
//   CSR/CSC via counting sort (fused histogram + single-pass scan);
//   gather accumulates fp32, writes out once.

typedef unsigned int u32;

#define MAXN 50048
#define MAXE 810000
#define D    96
#define D4   24
#define ALPHA 0.5f

// -------- static scratch --------
__device__ int   g_odeg [MAXN];
__device__ int   g_ideg [MAXN];
__device__ int   g_startR[MAXN];
__device__ int   g_startC[MAXN];
__device__ int   g_curR [MAXN];
__device__ int   g_curC [MAXN];
__device__ int   g_bsumR[256];
__device__ int   g_bsumC[256];
__device__ int2  g_pairR[MAXE];
__device__ int2  g_pairC[MAXE];
__device__ __align__(16) __half g_wh[192 * D];   // pre-scaled fp16 weights
__device__ __align__(16) __half g_xs[MAXN * D];
__device__ __align__(16) __half g_xt[MAXN * D];

// ---------------- mma helpers ----------------

__device__ __forceinline__ u32 s2u(const void* p) {
    return (u32)__cvta_generic_to_shared(p);
}

__device__ __forceinline__ void ldsm4(u32& r0, u32& r1, u32& r2, u32& r3, u32 addr) {
    asm volatile("ldmatrix.sync.aligned.m8n8.x4.shared.b16 {%0,%1,%2,%3}, [%4];"
                 : "=r"(r0), "=r"(r1), "=r"(r2), "=r"(r3) : "r"(addr));
}

__device__ __forceinline__ void mma16816(float& c0, float& c1, float& c2, float& c3,
                                         const u32* a, const u32* b) {
    asm volatile(
        "mma.sync.aligned.m16n8k16.row.col.f32.f16.f16.f32 "
        "{%0,%1,%2,%3}, {%4,%5,%6,%7}, {%8,%9}, {%0,%1,%2,%3};"
        : "+f"(c0), "+f"(c1), "+f"(c2), "+f"(c3)
        : "r"(a[0]), "r"(a[1]), "r"(a[2]), "r"(a[3]), "r"(b[0]), "r"(b[1]));
}

// ---------------- init: fp16 weights + zero degrees + zero block sums --------

__global__ void init_kernel(const float* __restrict__ Wsd,
                            const float* __restrict__ Wds, int N) {
    int i = blockIdx.x * blockDim.x + threadIdx.x;
    if (i < D * D) {
        g_wh[i]         = __float2half_rn(ALPHA          * Wsd[i]);
        g_wh[D * D + i] = __float2half_rn((1.0f - ALPHA) * Wds[i]);
    }
    if (i < N) { g_odeg[i] = 0; g_ideg[i] = 0; }
    if (i < 256) { g_bsumR[i] = 0; g_bsumC[i] = 0; }
}

// ---------------- degree + fused coarse histogram ----------------
// 256 threads, 8 edges/thread. Coarse bins (node>>8) accumulated in smem,
// flushed once per block -> g_bsum* hold per-256-node-range degree sums.

__global__ void deg_kernel(const int* __restrict__ ei, int E) {
    __shared__ int hR[256], hC[256];
    int t = threadIdx.x;
    hR[t] = 0; hC[t] = 0;
    __syncthreads();
    int base = blockIdx.x * 2048;
#pragma unroll
    for (int k = 0; k < 8; k++) {
        int e = base + k * 256 + t;
        if (e < E) {
            int r = ei[e];
            int c = ei[E + e];
            atomicAdd(&g_odeg[r], 1);
            atomicAdd(&g_ideg[c], 1);
            atomicAdd(&hR[r >> 8], 1);
            atomicAdd(&hC[c >> 8], 1);
        }
    }
    __syncthreads();
    if (hR[t]) atomicAdd(&g_bsumR[t], hR[t]);
    if (hC[t]) atomicAdd(&g_bsumC[t], hC[t]);
}

// ---------------- single-pass scan ----------------
// Every block redundantly scans the 256 block sums (cheap), picks its own
// exclusive offset, then scans its local 256 degrees and writes start/cur.

__device__ __forceinline__ int warp_incl_scan(int v) {
#pragma unroll
    for (int off = 1; off < 32; off <<= 1) {
        int a = __shfl_up_sync(0xffffffffu, v, off);
        if ((threadIdx.x & 31) >= off) v += a;
    }
    return v;
}

__global__ void scanA_kernel(int N) {
    __shared__ int wR[8], wC[8];
    __shared__ int inclR[256], inclC[256];
    int t = threadIdx.x, lane = t & 31, wid = t >> 5;

    // phase 1: redundant scan of the 256 coarse sums
    {
        int vR = g_bsumR[t];
        int vC = g_bsumC[t];
        int sR = warp_incl_scan(vR);
        int sC = warp_incl_scan(vC);
        if (lane == 31) { wR[wid] = sR; wC[wid] = sC; }
        __syncthreads();
        if (wid == 0) {
            int aR = (lane < 8) ? wR[lane] : 0;
            int aC = (lane < 8) ? wC[lane] : 0;
            aR = warp_incl_scan(aR);
            aC = warp_incl_scan(aC);
            if (lane < 8) { wR[lane] = aR; wC[lane] = aC; }
        }
        __syncthreads();
        int offR = (wid > 0) ? wR[wid - 1] : 0;
        int offC = (wid > 0) ? wC[wid - 1] : 0;
        inclR[t] = offR + sR;
        inclC[t] = offC + sC;
    }
    __syncthreads();
    int blkOffR = (blockIdx.x > 0) ? inclR[blockIdx.x - 1] : 0;
    int blkOffC = (blockIdx.x > 0) ? inclC[blockIdx.x - 1] : 0;
    __syncthreads();   // reuse wR/wC below

    // phase 2: local scan of this block's 256 degrees
    int i = blockIdx.x * 256 + t;
    int vR = (i < N) ? g_odeg[i] : 0;
    int vC = (i < N) ? g_ideg[i] : 0;
    int sR = warp_incl_scan(vR);
    int sC = warp_incl_scan(vC);
    if (lane == 31) { wR[wid] = sR; wC[wid] = sC; }
    __syncthreads();
    if (wid == 0) {
        int aR = (lane < 8) ? wR[lane] : 0;
        int aC = (lane < 8) ? wC[lane] : 0;
        aR = warp_incl_scan(aR);
        aC = warp_incl_scan(aC);
        if (lane < 8) { wR[lane] = aR; wC[lane] = aC; }
    }
    __syncthreads();
    int offR = (wid > 0) ? wR[wid - 1] : 0;
    int offC = (wid > 0) ? wC[wid - 1] : 0;
    if (i < N) {
        int aR = blkOffR + offR + sR - vR;
        int aC = blkOffC + offC + sC - vC;
        g_startR[i] = aR; g_curR[i] = aR;
        g_startC[i] = aC; g_curC[i] = aC;
    }
}

// ---------------- CSR/CSC build ----------------

__global__ void build_kernel(const int* __restrict__ ei, int E) {
    int e = blockIdx.x * blockDim.x + threadIdx.x;
    if (e >= E) return;
    int r = ei[e];
    int c = ei[E + e];
    float val = rsqrtf((float)g_odeg[r]) * rsqrtf((float)g_ideg[c]);
    int vb = __float_as_int(val);
    int pR = atomicAdd(&g_curR[r], 1);
    g_pairR[pR] = make_int2(c, vb);
    int pC = atomicAdd(&g_curC[c], 1);
    g_pairC[pC] = make_int2(r, vb);
}

// ---------------- HMMA GEMM ----------------
#define LDH 104   // padded halfs per smem row (208B stride: conflict-free ldmatrix)

__global__ void __launch_bounds__(256)
gemm_mma_kernel(const float* __restrict__ x, int N) {
    extern __shared__ __half sh[];
    __half* Xs = sh;               // [128][LDH]
    __half* Ws = sh + 128 * LDH;   // [192][LDH]

    int tid = threadIdx.x;
    int nb  = blockIdx.x * 128;

    const u32* w2 = (const u32*)g_wh;       // 192*48 half2
    for (int i = tid; i < 192 * 48; i += 256) {
        int r = i / 48, c = i % 48;
        *(u32*)&Ws[r * LDH + c * 2] = w2[i];
    }
    const float4* x4 = (const float4*)x;
    for (int i = tid; i < 128 * D4; i += 256) {
        int r = i / D4, c = i % D4;
        int n = nb + r;
        float4 v = (n < N) ? x4[n * D4 + c] : make_float4(0.f, 0.f, 0.f, 0.f);
        *(__half2*)&Xs[r * LDH + c * 4]     = __floats2half2_rn(v.x, v.y);
        *(__half2*)&Xs[r * LDH + c * 4 + 2] = __floats2half2_rn(v.z, v.w);
    }
    __syncthreads();

    int wid = tid >> 5, l = tid & 31;
    int mrow = wid * 16;

    u32 a[6][4];
    u32 a_addr0 = s2u(&Xs[(mrow + (l & 15)) * LDH + (l >> 4) * 8]);
#pragma unroll
    for (int s = 0; s < 6; s++)
        ldsm4(a[s][0], a[s][1], a[s][2], a[s][3], a_addr0 + s * 32);

    u32 b_addr0 = s2u(&Ws[(l & 7) * LDH + (l >> 3) * 8]);

    int r0n = nb + mrow + (l >> 2);
    int ccol = 2 * (l & 3);

#pragma unroll
    for (int nt = 0; nt < 24; nt++) {
        float c0 = 0.f, c1 = 0.f, c2 = 0.f, c3 = 0.f;
        u32 b[6][2];
#pragma unroll
        for (int j = 0; j < 3; j++) {
            u32 r0, r1, r2, r3;
            ldsm4(r0, r1, r2, r3, b_addr0 + nt * 8 * LDH * 2 + j * 64);
            b[2 * j][0] = r0; b[2 * j][1] = r1;
            b[2 * j + 1][0] = r2; b[2 * j + 1][1] = r3;
        }
#pragma unroll
        for (int s = 0; s < 6; s++)
            mma16816(c0, c1, c2, c3, a[s], b[s]);

        int c = nt * 8 + ccol;
        __half* dst = (c < D) ? g_xs : g_xt;
        int cc = (c < D) ? c : c - D;
        if (r0n < N)
            *(__half2*)&dst[r0n * D + cc] = __floats2half2_rn(c0, c1);
        if (r0n + 8 < N)
            *(__half2*)&dst[(r0n + 8) * D + cc] = __floats2half2_rn(c2, c3);
    }
}

// ---------------- fused gather ----------------

__device__ __forceinline__ void acc_msg(float4& acc, float v, uint2 u) {
    float2 a = __half22float2(*(__half2*)&u.x);
    float2 b = __half22float2(*(__half2*)&u.y);
    acc.x += v * a.x; acc.y += v * a.y;
    acc.z += v * b.x; acc.w += v * b.y;
}

__device__ __forceinline__ void gather_dir(float4& acc, const int2* __restrict__ pair,
                                           const uint2* __restrict__ msg,
                                           int s, int d, int lane) {
    int j = 0;
    for (; j + 8 <= d; j += 8) {
        int2 p[8]; uint2 m[8];
#pragma unroll
        for (int k = 0; k < 8; k++) p[k] = pair[s + j + k];
#pragma unroll
        for (int k = 0; k < 8; k++) m[k] = msg[p[k].x * D4 + lane];
#pragma unroll
        for (int k = 0; k < 8; k++) acc_msg(acc, __int_as_float(p[k].y), m[k]);
    }
    if (j + 4 <= d) {
        int2 p[4]; uint2 m[4];
#pragma unroll
        for (int k = 0; k < 4; k++) p[k] = pair[s + j + k];
#pragma unroll
        for (int k = 0; k < 4; k++) m[k] = msg[p[k].x * D4 + lane];
#pragma unroll
        for (int k = 0; k < 4; k++) acc_msg(acc, __int_as_float(p[k].y), m[k]);
        j += 4;
    }
    for (; j < d; j++) {
        int2 p = pair[s + j];
        acc_msg(acc, __int_as_float(p.y), msg[p.x * D4 + lane]);
    }
}

__global__ void gather_kernel(float* __restrict__ out,
                              const float* __restrict__ b_sd,
                              const float* __restrict__ b_ds,
                              int N) {
    int warp = (blockIdx.x * blockDim.x + threadIdx.x) >> 5;
    int lane = threadIdx.x & 31;
    if (warp >= N || lane >= D4) return;
    int n = warp;

    float4 acc = make_float4(0.f, 0.f, 0.f, 0.f);

    gather_dir(acc, g_pairR, (const uint2*)g_xs, g_startR[n], g_odeg[n], lane);
    gather_dir(acc, g_pairC, (const uint2*)g_xt, g_startC[n], g_ideg[n], lane);

    float4 bs = ((const float4*)b_sd)[lane];
    float4 bd = ((const float4*)b_ds)[lane];
    float4 o;
    o.x = acc.x + ALPHA * bs.x + (1.0f - ALPHA) * bd.x;
    o.y = acc.y + ALPHA * bs.y + (1.0f - ALPHA) * bd.y;
    o.z = acc.z + ALPHA * bs.z + (1.0f - ALPHA) * bd.z;
    o.w = acc.w + ALPHA * bs.w + (1.0f - ALPHA) * bd.w;
    ((float4*)out)[n * D4 + lane] = o;
}

// ---------------- launch ----------------

extern "C" void kernel_launch(void* const* d_in, const int* in_sizes, int n_in,
                              void* d_out, int out_size) {
    const float* x    = (const float*)d_in[0];
    const float* Wsd  = (const float*)d_in[1];
    const float* b_sd = (const float*)d_in[2];
    const float* Wds  = (const float*)d_in[3];
    const float* b_ds = (const float*)d_in[4];
    const int*   ei   = (const int*)  d_in[5];
    float* out = (float*)d_out;

    int N = in_sizes[0] / D;
    int E = in_sizes[5] / 2;

    size_t smem = (size_t)(128 + 192) * LDH * sizeof(__half);   // 66560 B
    cudaFuncSetAttribute(gemm_mma_kernel,
                         cudaFuncAttributeMaxDynamicSharedMemorySize, (int)smem);

    int nScan = (N + 255) / 256;

    init_kernel <<<(N + 255) / 256, 256>>>(Wsd, Wds, N);            // idx 0
    deg_kernel  <<<(E + 2047) / 2048, 256>>>(ei, E);                // idx 1
    scanA_kernel<<<nScan, 256>>>(N);                                // idx 2
    gemm_mma_kernel<<<(N + 127) / 128, 256, smem>>>(x, N);          // idx 3 (profiled)
    build_kernel<<<(E + 255) / 256, 256>>>(ei, E);                  // idx 4
    long long gthreads = (long long)N * 32;
    gather_kernel<<<(int)((gthreads + 255) / 256), 256>>>(out, b_sd, b_ds, N);  // idx 5
}

// round 8
// speedup vs baseline: 2.6041x; 1.1259x over previous
#include <cuda_runtime.h>
#include <cuda_fp16.h>
#include <cstdint>

// DirGCNConv:
//   xs = x @ (a*Wsd)^T ; xt = x @ ((1-a)*Wds)^T    (HMMA fp16 GEMM, fp32 acc)
//   CSR/CSC via counting sort (fused histogram + single-pass scan);
//   gather accumulates fp32, writes out once.
// GEMM runs on a forked stream, overlapped with graph prep (deg/scan/build).

typedef unsigned int u32;

#define MAXN 50048
#define MAXE 810000
#define D    96
#define D4   24
#define ALPHA 0.5f

// -------- static scratch --------
__device__ int   g_odeg [MAXN];
__device__ int   g_ideg [MAXN];
__device__ int   g_startR[MAXN];
__device__ int   g_startC[MAXN];
__device__ int   g_curR [MAXN];
__device__ int   g_curC [MAXN];
__device__ int   g_bsumR[256];
__device__ int   g_bsumC[256];
__device__ int2  g_pairR[MAXE];
__device__ int2  g_pairC[MAXE];
__device__ __align__(16) __half g_wh[192 * D];   // pre-scaled fp16 weights
__device__ __align__(16) __half g_xs[MAXN * D];
__device__ __align__(16) __half g_xt[MAXN * D];

// ---------------- mma helpers ----------------

__device__ __forceinline__ u32 s2u(const void* p) {
    return (u32)__cvta_generic_to_shared(p);
}

__device__ __forceinline__ void ldsm4(u32& r0, u32& r1, u32& r2, u32& r3, u32 addr) {
    asm volatile("ldmatrix.sync.aligned.m8n8.x4.shared.b16 {%0,%1,%2,%3}, [%4];"
                 : "=r"(r0), "=r"(r1), "=r"(r2), "=r"(r3) : "r"(addr));
}

__device__ __forceinline__ void mma16816(float& c0, float& c1, float& c2, float& c3,
                                         const u32* a, const u32* b) {
    asm volatile(
        "mma.sync.aligned.m16n8k16.row.col.f32.f16.f16.f32 "
        "{%0,%1,%2,%3}, {%4,%5,%6,%7}, {%8,%9}, {%0,%1,%2,%3};"
        : "+f"(c0), "+f"(c1), "+f"(c2), "+f"(c3)
        : "r"(a[0]), "r"(a[1]), "r"(a[2]), "r"(a[3]), "r"(b[0]), "r"(b[1]));
}

// ---------------- init: fp16 weights + zero degrees + zero block sums --------

__global__ void init_kernel(const float* __restrict__ Wsd,
                            const float* __restrict__ Wds, int N) {
    int i = blockIdx.x * blockDim.x + threadIdx.x;
    if (i < D * D) {
        g_wh[i]         = __float2half_rn(ALPHA          * Wsd[i]);
        g_wh[D * D + i] = __float2half_rn((1.0f - ALPHA) * Wds[i]);
    }
    if (i < N) { g_odeg[i] = 0; g_ideg[i] = 0; }
    if (i < 256) { g_bsumR[i] = 0; g_bsumC[i] = 0; }
}

// ---------------- degree + fused coarse histogram ----------------

__global__ void deg_kernel(const int* __restrict__ ei, int E) {
    __shared__ int hR[256], hC[256];
    int t = threadIdx.x;
    hR[t] = 0; hC[t] = 0;
    __syncthreads();
    int base = blockIdx.x * 2048;
#pragma unroll
    for (int k = 0; k < 8; k++) {
        int e = base + k * 256 + t;
        if (e < E) {
            int r = ei[e];
            int c = ei[E + e];
            atomicAdd(&g_odeg[r], 1);
            atomicAdd(&g_ideg[c], 1);
            atomicAdd(&hR[r >> 8], 1);
            atomicAdd(&hC[c >> 8], 1);
        }
    }
    __syncthreads();
    if (hR[t]) atomicAdd(&g_bsumR[t], hR[t]);
    if (hC[t]) atomicAdd(&g_bsumC[t], hC[t]);
}

// ---------------- single-pass scan ----------------

__device__ __forceinline__ int warp_incl_scan(int v) {
#pragma unroll
    for (int off = 1; off < 32; off <<= 1) {
        int a = __shfl_up_sync(0xffffffffu, v, off);
        if ((threadIdx.x & 31) >= off) v += a;
    }
    return v;
}

__global__ void scanA_kernel(int N) {
    __shared__ int wR[8], wC[8];
    __shared__ int inclR[256], inclC[256];
    int t = threadIdx.x, lane = t & 31, wid = t >> 5;

    {
        int vR = g_bsumR[t];
        int vC = g_bsumC[t];
        int sR = warp_incl_scan(vR);
        int sC = warp_incl_scan(vC);
        if (lane == 31) { wR[wid] = sR; wC[wid] = sC; }
        __syncthreads();
        if (wid == 0) {
            int aR = (lane < 8) ? wR[lane] : 0;
            int aC = (lane < 8) ? wC[lane] : 0;
            aR = warp_incl_scan(aR);
            aC = warp_incl_scan(aC);
            if (lane < 8) { wR[lane] = aR; wC[lane] = aC; }
        }
        __syncthreads();
        int offR = (wid > 0) ? wR[wid - 1] : 0;
        int offC = (wid > 0) ? wC[wid - 1] : 0;
        inclR[t] = offR + sR;
        inclC[t] = offC + sC;
    }
    __syncthreads();
    int blkOffR = (blockIdx.x > 0) ? inclR[blockIdx.x - 1] : 0;
    int blkOffC = (blockIdx.x > 0) ? inclC[blockIdx.x - 1] : 0;
    __syncthreads();

    int i = blockIdx.x * 256 + t;
    int vR = (i < N) ? g_odeg[i] : 0;
    int vC = (i < N) ? g_ideg[i] : 0;
    int sR = warp_incl_scan(vR);
    int sC = warp_incl_scan(vC);
    if (lane == 31) { wR[wid] = sR; wC[wid] = sC; }
    __syncthreads();
    if (wid == 0) {
        int aR = (lane < 8) ? wR[lane] : 0;
        int aC = (lane < 8) ? wC[lane] : 0;
        aR = warp_incl_scan(aR);
        aC = warp_incl_scan(aC);
        if (lane < 8) { wR[lane] = aR; wC[lane] = aC; }
    }
    __syncthreads();
    int offR = (wid > 0) ? wR[wid - 1] : 0;
    int offC = (wid > 0) ? wC[wid - 1] : 0;
    if (i < N) {
        int aR = blkOffR + offR + sR - vR;
        int aC = blkOffC + offC + sC - vC;
        g_startR[i] = aR; g_curR[i] = aR;
        g_startC[i] = aC; g_curC[i] = aC;
    }
}

// ---------------- CSR/CSC build ----------------

__global__ void build_kernel(const int* __restrict__ ei, int E) {
    int e = blockIdx.x * blockDim.x + threadIdx.x;
    if (e >= E) return;
    int r = ei[e];
    int c = ei[E + e];
    float val = rsqrtf((float)g_odeg[r]) * rsqrtf((float)g_ideg[c]);
    int vb = __float_as_int(val);
    int pR = atomicAdd(&g_curR[r], 1);
    g_pairR[pR] = make_int2(c, vb);
    int pC = atomicAdd(&g_curC[c], 1);
    g_pairC[pC] = make_int2(r, vb);
}

// ---------------- HMMA GEMM: 256-node tile ----------------
// 256 threads (8 warps); warp w: rows w*32..w*32+31 (2 m16 tiles) x 24 n8 tiles.
// B fragments loaded once per n-tile, reused by both m-tiles.
#define LDH 104   // 208B row stride: conflict-free ldmatrix

__global__ void __launch_bounds__(256)
gemm_mma_kernel(const float* __restrict__ x, int N) {
    extern __shared__ __half sh[];
    __half* Xs = sh;               // [256][LDH]
    __half* Ws = sh + 256 * LDH;   // [192][LDH]

    int tid = threadIdx.x;
    int nb  = blockIdx.x * 256;

    const u32* w2 = (const u32*)g_wh;       // 192*48 half2
    for (int i = tid; i < 192 * 48; i += 256) {
        int r = i / 48, c = i % 48;
        *(u32*)&Ws[r * LDH + c * 2] = w2[i];
    }
    const float4* x4 = (const float4*)x;
    for (int i = tid; i < 256 * D4; i += 256) {
        int r = i / D4, c = i % D4;
        int n = nb + r;
        float4 v = (n < N) ? x4[n * D4 + c] : make_float4(0.f, 0.f, 0.f, 0.f);
        *(__half2*)&Xs[r * LDH + c * 4]     = __floats2half2_rn(v.x, v.y);
        *(__half2*)&Xs[r * LDH + c * 4 + 2] = __floats2half2_rn(v.z, v.w);
    }
    __syncthreads();

    int wid = tid >> 5, l = tid & 31;
    int mbase = wid * 32;

    // A fragments: 2 m-tiles x 6 k-steps
    u32 a[2][6][4];
#pragma unroll
    for (int mi = 0; mi < 2; mi++) {
        u32 a_addr = s2u(&Xs[(mbase + mi * 16 + (l & 15)) * LDH + (l >> 4) * 8]);
#pragma unroll
        for (int s = 0; s < 6; s++)
            ldsm4(a[mi][s][0], a[mi][s][1], a[mi][s][2], a[mi][s][3],
                  a_addr + s * 32);
    }

    u32 b_addr0 = s2u(&Ws[(l & 7) * LDH + (l >> 3) * 8]);

    int rq = l >> 2;          // quad row
    int ccol = 2 * (l & 3);

#pragma unroll
    for (int nt = 0; nt < 24; nt++) {
        u32 b[6][2];
#pragma unroll
        for (int j = 0; j < 3; j++) {
            u32 r0, r1, r2, r3;
            ldsm4(r0, r1, r2, r3, b_addr0 + nt * 8 * LDH * 2 + j * 64);
            b[2 * j][0] = r0; b[2 * j][1] = r1;
            b[2 * j + 1][0] = r2; b[2 * j + 1][1] = r3;
        }
        int c = nt * 8 + ccol;
        __half* dst = (c < D) ? g_xs : g_xt;
        int cc = (c < D) ? c : c - D;
#pragma unroll
        for (int mi = 0; mi < 2; mi++) {
            float c0 = 0.f, c1 = 0.f, c2 = 0.f, c3 = 0.f;
#pragma unroll
            for (int s = 0; s < 6; s++)
                mma16816(c0, c1, c2, c3, a[mi][s], b[s]);
            int r0n = nb + mbase + mi * 16 + rq;
            if (r0n < N)
                *(__half2*)&dst[r0n * D + cc] = __floats2half2_rn(c0, c1);
            if (r0n + 8 < N)
                *(__half2*)&dst[(r0n + 8) * D + cc] = __floats2half2_rn(c2, c3);
        }
    }
}

// ---------------- fused gather ----------------

__device__ __forceinline__ void acc_msg(float4& acc, float v, uint2 u) {
    float2 a = __half22float2(*(__half2*)&u.x);
    float2 b = __half22float2(*(__half2*)&u.y);
    acc.x += v * a.x; acc.y += v * a.y;
    acc.z += v * b.x; acc.w += v * b.y;
}

__device__ __forceinline__ void gather_dir(float4& acc, const int2* __restrict__ pair,
                                           const uint2* __restrict__ msg,
                                           int s, int d, int lane) {
    int j = 0;
    for (; j + 8 <= d; j += 8) {
        int2 p[8]; uint2 m[8];
#pragma unroll
        for (int k = 0; k < 8; k++) p[k] = pair[s + j + k];
#pragma unroll
        for (int k = 0; k < 8; k++) m[k] = msg[p[k].x * D4 + lane];
#pragma unroll
        for (int k = 0; k < 8; k++) acc_msg(acc, __int_as_float(p[k].y), m[k]);
    }
    if (j + 4 <= d) {
        int2 p[4]; uint2 m[4];
#pragma unroll
        for (int k = 0; k < 4; k++) p[k] = pair[s + j + k];
#pragma unroll
        for (int k = 0; k < 4; k++) m[k] = msg[p[k].x * D4 + lane];
#pragma unroll
        for (int k = 0; k < 4; k++) acc_msg(acc, __int_as_float(p[k].y), m[k]);
        j += 4;
    }
    for (; j < d; j++) {
        int2 p = pair[s + j];
        acc_msg(acc, __int_as_float(p.y), msg[p.x * D4 + lane]);
    }
}

__global__ void gather_kernel(float* __restrict__ out,
                              const float* __restrict__ b_sd,
                              const float* __restrict__ b_ds,
                              int N) {
    int warp = (blockIdx.x * blockDim.x + threadIdx.x) >> 5;
    int lane = threadIdx.x & 31;
    if (warp >= N || lane >= D4) return;
    int n = warp;

    float4 acc = make_float4(0.f, 0.f, 0.f, 0.f);

    gather_dir(acc, g_pairR, (const uint2*)g_xs, g_startR[n], g_odeg[n], lane);
    gather_dir(acc, g_pairC, (const uint2*)g_xt, g_startC[n], g_ideg[n], lane);

    float4 bs = ((const float4*)b_sd)[lane];
    float4 bd = ((const float4*)b_ds)[lane];
    float4 o;
    o.x = acc.x + ALPHA * bs.x + (1.0f - ALPHA) * bd.x;
    o.y = acc.y + ALPHA * bs.y + (1.0f - ALPHA) * bd.y;
    o.z = acc.z + ALPHA * bs.z + (1.0f - ALPHA) * bd.z;
    o.w = acc.w + ALPHA * bs.w + (1.0f - ALPHA) * bd.w;
    ((float4*)out)[n * D4 + lane] = o;
}

// ---------------- launch ----------------
// Fork-join: gemm on a side stream, overlapped with deg/scan/build on the
// main stream. Stream/events created once on the first (non-captured)
// correctness call; captured calls only record/wait (capturable ops).

static cudaStream_t g_s2  = 0;
static cudaEvent_t  g_evA = 0, g_evB = 0;

extern "C" void kernel_launch(void* const* d_in, const int* in_sizes, int n_in,
                              void* d_out, int out_size) {
    const float* x    = (const float*)d_in[0];
    const float* Wsd  = (const float*)d_in[1];
    const float* b_sd = (const float*)d_in[2];
    const float* Wds  = (const float*)d_in[3];
    const float* b_ds = (const float*)d_in[4];
    const int*   ei   = (const int*)  d_in[5];
    float* out = (float*)d_out;

    int N = in_sizes[0] / D;
    int E = in_sizes[5] / 2;

    if (!g_s2) {
        cudaStreamCreateWithFlags(&g_s2, cudaStreamNonBlocking);
        cudaEventCreateWithFlags(&g_evA, cudaEventDisableTiming);
        cudaEventCreateWithFlags(&g_evB, cudaEventDisableTiming);
    }

    size_t smem = (size_t)(256 + 192) * LDH * sizeof(__half);   // 93184 B
    cudaFuncSetAttribute(gemm_mma_kernel,
                         cudaFuncAttributeMaxDynamicSharedMemorySize, (int)smem);

    int nScan = (N + 255) / 256;

    init_kernel<<<(N + 255) / 256, 256>>>(Wsd, Wds, N);

    // fork: gemm depends only on init
    cudaEventRecord(g_evA, 0);
    cudaStreamWaitEvent(g_s2, g_evA, 0);
    gemm_mma_kernel<<<(N + 255) / 256, 256, smem, g_s2>>>(x, N);
    cudaEventRecord(g_evB, g_s2);

    // graph prep on main stream (overlaps with gemm)
    deg_kernel  <<<(E + 2047) / 2048, 256>>>(ei, E);
    scanA_kernel<<<nScan, 256>>>(N);
    build_kernel<<<(E + 255) / 256, 256>>>(ei, E);

    // join: gather needs both
    cudaStreamWaitEvent(0, g_evB, 0);
    long long gthreads = (long long)N * 32;
    gather_kernel<<<(int)((gthreads + 255) / 256), 256>>>(out, b_sd, b_ds, N);
}